// round 1
// baseline (speedup 1.0000x reference)
#include <cuda_runtime.h>
#include <math.h>

#define BATCH 256
#define NU    300
#define LIN   608
#define FLT   19
#define POOL  7
#define LP    84
#define HID   100
#define NCLS  50
#define EPSV  1e-5f

#define UPB 60          // units per block in conv kernel
#define TA  96          // conv kernel block size (84 active)

// scratch (device globals: no allocation allowed)
__device__ float g_y[NU * LP * BATCH];   // [u][f][b]
__device__ float g_z[NU * BATCH];        // [u][b]

// ---------------------------------------------------------------------------
// Kernel A: conv(4->U, k=19) + bias + BN + exp + maxpool(7)  ->  y[u][f][b]
// grid (NU/UPB, BATCH), block TA. Thread t owns pooled position t (t<84).
// x window (4ch x 25) cached in registers once, reused across UPB units.
// exp(max(..)) == max(exp(..)) since BN scale > 0.
// ---------------------------------------------------------------------------
__global__ __launch_bounds__(TA) void conv_pool_kernel(
    const float* __restrict__ x,  const float* __restrict__ w1,
    const float* __restrict__ b1, const float* __restrict__ g1,
    const float* __restrict__ be1,const float* __restrict__ m1,
    const float* __restrict__ v1)
{
    __shared__ float xs[4 * LIN];
    __shared__ float w1s[UPB * 4 * FLT];
    __shared__ float s1s[UPB], c1s[UPB];

    const int b   = blockIdx.y;
    const int u0  = blockIdx.x * UPB;
    const int tid = threadIdx.x;

    for (int i = tid; i < 4 * LIN; i += TA)
        xs[i] = x[b * 4 * LIN + i];
    for (int i = tid; i < UPB * 4 * FLT; i += TA)
        w1s[i] = w1[u0 * 4 * FLT + i];
    if (tid < UPB) {
        const int u = u0 + tid;
        float s = g1[u] * rsqrtf(v1[u] + EPSV);
        s1s[tid] = s;
        c1s[tid] = (b1[u] - m1[u]) * s + be1[u];
    }
    __syncthreads();

    if (tid >= LP) return;

    // register-cached x window: positions [7t, 7t+24] for 4 channels
    float xr[4][POOL + FLT - 1];
#pragma unroll
    for (int c = 0; c < 4; c++)
#pragma unroll
        for (int j = 0; j < POOL + FLT - 1; j++)
            xr[c][j] = xs[c * LIN + tid * POOL + j];

    for (int uu = 0; uu < UPB; uu++) {
        float acc[POOL];
#pragma unroll
        for (int q = 0; q < POOL; q++) acc[q] = 0.0f;

        const float* wp = &w1s[uu * 4 * FLT];
#pragma unroll
        for (int c = 0; c < 4; c++) {
#pragma unroll
            for (int k = 0; k < FLT; k++) {
                const float wv = wp[c * FLT + k];
#pragma unroll
                for (int q = 0; q < POOL; q++)
                    acc[q] = fmaf(xr[c][q + k], wv, acc[q]);
            }
        }
        float mx = acc[0];
#pragma unroll
        for (int q = 1; q < POOL; q++) mx = fmaxf(mx, acc[q]);

        const float yv = expf(fmaf(mx, s1s[uu], c1s[uu]));
        g_y[(u0 + uu) * (LP * BATCH) + tid * BATCH + b] = yv;
    }
}

// ---------------------------------------------------------------------------
// Kernel B: per-unit MLP 84->100 (BN+ReLU) -> 100->1 (BN+ReLU)  ->  z[u][b]
// grid NU, block BATCH. Thread = batch element, y row in 84 registers.
// ---------------------------------------------------------------------------
__global__ __launch_bounds__(BATCH) void unit_mlp_kernel(
    const float* __restrict__ w2, const float* __restrict__ b2,
    const float* __restrict__ g2, const float* __restrict__ be2,
    const float* __restrict__ m2, const float* __restrict__ v2,
    const float* __restrict__ w3, const float* __restrict__ b3,
    const float* __restrict__ g3, const float* __restrict__ be3,
    const float* __restrict__ m3, const float* __restrict__ v3)
{
    __shared__ __align__(16) float w2s[HID * LP];
    __shared__ float s2s[HID], c2s[HID], w3s[HID];

    const int u   = blockIdx.x;
    const int tid = threadIdx.x;

    for (int i = tid; i < HID * LP; i += BATCH)
        w2s[i] = w2[u * HID * LP + i];
    if (tid < HID) {
        const int idx = u * HID + tid;
        float s = g2[idx] * rsqrtf(v2[idx] + EPSV);
        s2s[tid] = s;
        c2s[tid] = (b2[idx] - m2[idx]) * s + be2[idx];
        w3s[tid] = w3[idx];
    }
    __syncthreads();

    float yv[LP];
#pragma unroll
    for (int f = 0; f < LP; f++)
        yv[f] = g_y[u * (LP * BATCH) + f * BATCH + tid];

    float zacc = 0.0f;
    for (int o = 0; o < HID; o++) {
        const float4* wrow = reinterpret_cast<const float4*>(&w2s[o * LP]);
        float d0 = 0.0f, d1 = 0.0f;
#pragma unroll
        for (int f4 = 0; f4 < LP / 8; f4++) {
            float4 a = wrow[2 * f4];
            float4 b4 = wrow[2 * f4 + 1];
            d0 = fmaf(yv[8 * f4 + 0], a.x, d0);
            d1 = fmaf(yv[8 * f4 + 1], a.y, d1);
            d0 = fmaf(yv[8 * f4 + 2], a.z, d0);
            d1 = fmaf(yv[8 * f4 + 3], a.w, d1);
            d0 = fmaf(yv[8 * f4 + 4], b4.x, d0);
            d1 = fmaf(yv[8 * f4 + 5], b4.y, d1);
            d0 = fmaf(yv[8 * f4 + 6], b4.z, d0);
            d1 = fmaf(yv[8 * f4 + 7], b4.w, d1);
        }
        // LP=84: remainder 4 floats
        {
            float4 a = wrow[20];
            d0 = fmaf(yv[80], a.x, d0);
            d1 = fmaf(yv[81], a.y, d1);
            d0 = fmaf(yv[82], a.z, d0);
            d1 = fmaf(yv[83], a.w, d1);
        }
        const float d = d0 + d1;
        const float hv = fmaxf(fmaf(d, s2s[o], c2s[o]), 0.0f);
        zacc = fmaf(hv, w3s[o], zacc);
    }

    const float s3 = g3[u] * rsqrtf(v3[u] + EPSV);
    const float z  = fmaf(zacc + b3[u] - m3[u], s3, be3[u]);
    g_z[u * BATCH + tid] = fmaxf(z, 0.0f);
}

// ---------------------------------------------------------------------------
// Kernel C: out[b][c] = sum_u z[u][b] * wf[c][u] + bf[c]
// grid NCLS, block BATCH.
// ---------------------------------------------------------------------------
__global__ __launch_bounds__(BATCH) void final_linear_kernel(
    const float* __restrict__ wf, const float* __restrict__ bf,
    float* __restrict__ out)
{
    __shared__ float wfs[NU];
    const int c   = blockIdx.x;
    const int tid = threadIdx.x;

    for (int i = tid; i < NU; i += BATCH)
        wfs[i] = wf[c * NU + i];
    __syncthreads();

    float acc = bf[c];
#pragma unroll 4
    for (int u = 0; u < NU; u++)
        acc = fmaf(g_z[u * BATCH + tid], wfs[u], acc);

    out[tid * NCLS + c] = acc;
}

// ---------------------------------------------------------------------------
extern "C" void kernel_launch(void* const* d_in, const int* in_sizes, int n_in,
                              void* d_out, int out_size)
{
    const float* x   = (const float*)d_in[0];
    const float* w1  = (const float*)d_in[1];
    const float* b1  = (const float*)d_in[2];
    const float* g1  = (const float*)d_in[3];
    const float* be1 = (const float*)d_in[4];
    const float* m1  = (const float*)d_in[5];
    const float* v1  = (const float*)d_in[6];
    const float* w2  = (const float*)d_in[7];
    const float* b2  = (const float*)d_in[8];
    const float* g2  = (const float*)d_in[9];
    const float* be2 = (const float*)d_in[10];
    const float* m2  = (const float*)d_in[11];
    const float* v2  = (const float*)d_in[12];
    const float* w3  = (const float*)d_in[13];
    const float* b3  = (const float*)d_in[14];
    const float* g3  = (const float*)d_in[15];
    const float* m3g = nullptr; (void)m3g;
    const float* be3 = (const float*)d_in[16];
    const float* m3  = (const float*)d_in[17];
    const float* v3  = (const float*)d_in[18];
    const float* wf  = (const float*)d_in[19];
    const float* bf  = (const float*)d_in[20];
    float* out = (float*)d_out;

    conv_pool_kernel<<<dim3(NU / UPB, BATCH), TA>>>(x, w1, b1, g1, be1, m1, v1);
    unit_mlp_kernel<<<NU, BATCH>>>(w2, b2, g2, be2, m2, v2,
                                   w3, b3, g3, be3, m3, v3);
    final_linear_kernel<<<NCLS, BATCH>>>(wf, bf, out);
}

// round 2
// speedup vs baseline: 1.0486x; 1.0486x over previous
#include <cuda_runtime.h>
#include <math.h>

#define BATCH 256
#define NU    300
#define LIN   608
#define FLT   19
#define POOL  7
#define LP    84
#define HID   100
#define NCLS  50
#define EPSV  1e-5f

#define UPB 60          // units per block in conv kernel (30 pairs)
#define TA  96          // conv kernel block size (84 active)

typedef unsigned long long u64;

// ---- packed f32x2 helpers -------------------------------------------------
__device__ __forceinline__ u64 pack_dup(float v) {
    u64 r; unsigned u = __float_as_uint(v);
    asm("mov.b64 %0, {%1, %1};" : "=l"(r) : "r"(u));
    return r;
}
__device__ __forceinline__ u64 pack2(float a, float b) {
    u64 r;
    asm("mov.b64 %0, {%1, %2};" : "=l"(r) : "f"(a), "f"(b));
    return r;
}
__device__ __forceinline__ void fma2(u64 &d, u64 a, u64 b) {
    asm("fma.rn.f32x2 %0, %1, %2, %0;" : "+l"(d) : "l"(a), "l"(b));
}
__device__ __forceinline__ void unpack2(float &lo, float &hi, u64 v) {
    unsigned a, b;
    asm("mov.b64 {%0, %1}, %2;" : "=r"(a), "=r"(b) : "l"(v));
    lo = __uint_as_float(a); hi = __uint_as_float(b);
}

// scratch (device globals: no allocation allowed)
__device__ float g_y[NU * LP * BATCH];   // [u][f][b]
__device__ float g_z[NU * BATCH];        // [u][b]

// ---------------------------------------------------------------------------
// Kernel A: conv(4->U, k=19) + bias + BN + exp + maxpool(7)  ->  y[u][f][b]
// Unit-PAIR packed FFMA2: weights interleaved {w_u0,w_u1} in shared (LDS.64),
// x window duplicated {x,x} in registers (built once, reused for 30 pairs).
// ---------------------------------------------------------------------------
__global__ __launch_bounds__(TA, 1) void conv_pool_kernel(
    const float* __restrict__ x,  const float* __restrict__ w1,
    const float* __restrict__ b1, const float* __restrict__ g1,
    const float* __restrict__ be1,const float* __restrict__ m1,
    const float* __restrict__ v1)
{
    __shared__ float xs[4 * LIN];
    __shared__ __align__(16) float w1s[UPB * 4 * FLT];  // interleaved pairs
    __shared__ float s1s[UPB], c1s[UPB];

    const int b   = blockIdx.y;
    const int u0  = blockIdx.x * UPB;
    const int tid = threadIdx.x;

    for (int i = tid; i < 4 * LIN; i += TA)
        xs[i] = x[b * 4 * LIN + i];
    // interleave: w1s[(pair*76 + ck)*2 + lane] = w1[(u0+ul)*76 + ck]
    for (int i = tid; i < UPB * 4 * FLT; i += TA) {
        const int ul = i / (4 * FLT);
        const int ck = i % (4 * FLT);
        w1s[((ul >> 1) * (4 * FLT) + ck) * 2 + (ul & 1)] =
            w1[(u0 + ul) * (4 * FLT) + ck];
    }
    if (tid < UPB) {
        const int u = u0 + tid;
        float s = g1[u] * rsqrtf(v1[u] + EPSV);
        s1s[tid] = s;
        c1s[tid] = (b1[u] - m1[u]) * s + be1[u];
    }
    __syncthreads();

    if (tid >= LP) return;

    // register-cached duplicated x window: {x,x} for positions [7t, 7t+24]
    u64 xr2[4][POOL + FLT - 1];
#pragma unroll
    for (int c = 0; c < 4; c++)
#pragma unroll
        for (int j = 0; j < POOL + FLT - 1; j++)
            xr2[c][j] = pack_dup(xs[c * LIN + tid * POOL + j]);

    const u64* wpairs = reinterpret_cast<const u64*>(w1s);
    const long ybase = (long)u0 * (LP * BATCH) + (long)tid * BATCH + b;

#pragma unroll 1
    for (int p = 0; p < UPB / 2; p++) {
        u64 acc2[POOL];
#pragma unroll
        for (int q = 0; q < POOL; q++) acc2[q] = 0ULL;

        const u64* wp = wpairs + p * (4 * FLT);
#pragma unroll
        for (int c = 0; c < 4; c++) {
#pragma unroll
            for (int k = 0; k < FLT; k++) {
                const u64 wv = wp[c * FLT + k];
#pragma unroll
                for (int q = 0; q < POOL; q++)
                    fma2(acc2[q], xr2[c][q + k], wv);
            }
        }
        float lo, hi, mx0, mx1;
        unpack2(mx0, mx1, acc2[0]);
#pragma unroll
        for (int q = 1; q < POOL; q++) {
            unpack2(lo, hi, acc2[q]);
            mx0 = fmaxf(mx0, lo);
            mx1 = fmaxf(mx1, hi);
        }
        const int ua = 2 * p;
        g_y[ybase + (long)ua * (LP * BATCH)] =
            __expf(fmaf(mx0, s1s[ua], c1s[ua]));
        g_y[ybase + (long)(ua + 1) * (LP * BATCH)] =
            __expf(fmaf(mx1, s1s[ua + 1], c1s[ua + 1]));
    }
}

// ---------------------------------------------------------------------------
// Kernel B: per-unit MLP 84->100 (BN+ReLU) -> 100->1 (BN+ReLU)  ->  z[u][b]
// f-pair packed FFMA2: yv2[fp]={y[2f],y[2f+1]} in regs, w row via LDS.128.
// ---------------------------------------------------------------------------
__global__ __launch_bounds__(BATCH) void unit_mlp_kernel(
    const float* __restrict__ w2, const float* __restrict__ b2,
    const float* __restrict__ g2, const float* __restrict__ be2,
    const float* __restrict__ m2, const float* __restrict__ v2,
    const float* __restrict__ w3, const float* __restrict__ b3,
    const float* __restrict__ g3, const float* __restrict__ be3,
    const float* __restrict__ m3, const float* __restrict__ v3)
{
    __shared__ __align__(16) float w2s[HID * LP];
    __shared__ float s2s[HID], c2s[HID], w3s[HID];

    const int u   = blockIdx.x;
    const int tid = threadIdx.x;

    for (int i = tid; i < HID * LP; i += BATCH)
        w2s[i] = w2[u * HID * LP + i];
    if (tid < HID) {
        const int idx = u * HID + tid;
        float s = g2[idx] * rsqrtf(v2[idx] + EPSV);
        s2s[tid] = s;
        c2s[tid] = (b2[idx] - m2[idx]) * s + be2[idx];
        w3s[tid] = w3[idx];
    }
    __syncthreads();

    // packed y: {y[2f], y[2f+1]}
    u64 yv2[LP / 2];
#pragma unroll
    for (int fp = 0; fp < LP / 2; fp++) {
        const float a = g_y[u * (LP * BATCH) + (2 * fp) * BATCH + tid];
        const float bb = g_y[u * (LP * BATCH) + (2 * fp + 1) * BATCH + tid];
        yv2[fp] = pack2(a, bb);
    }

    float zacc = 0.0f;
#pragma unroll 1
    for (int o = 0; o < HID; o++) {
        const float4* wrow = reinterpret_cast<const float4*>(&w2s[o * LP]);
        u64 a0 = 0ULL, a1 = 0ULL;
#pragma unroll
        for (int j = 0; j < LP / 4; j++) {   // 21 LDS.128
            float4 v = wrow[j];
            u64 w01 = pack2(v.x, v.y);
            u64 w23 = pack2(v.z, v.w);
            fma2(a0, yv2[2 * j], w01);
            fma2(a1, yv2[2 * j + 1], w23);
        }
        float l0, h0, l1, h1;
        unpack2(l0, h0, a0);
        unpack2(l1, h1, a1);
        const float d = (l0 + h0) + (l1 + h1);
        const float hv = fmaxf(fmaf(d, s2s[o], c2s[o]), 0.0f);
        zacc = fmaf(hv, w3s[o], zacc);
    }

    const float s3 = g3[u] * rsqrtf(v3[u] + EPSV);
    const float z  = fmaf(zacc + b3[u] - m3[u], s3, be3[u]);
    g_z[u * BATCH + tid] = fmaxf(z, 0.0f);
}

// ---------------------------------------------------------------------------
// Kernel C: out[b][c] = sum_u z[u][b] * wf[c][u] + bf[c]
// ---------------------------------------------------------------------------
__global__ __launch_bounds__(BATCH) void final_linear_kernel(
    const float* __restrict__ wf, const float* __restrict__ bf,
    float* __restrict__ out)
{
    __shared__ float wfs[NU];
    const int c   = blockIdx.x;
    const int tid = threadIdx.x;

    for (int i = tid; i < NU; i += BATCH)
        wfs[i] = wf[c * NU + i];
    __syncthreads();

    float acc = bf[c];
#pragma unroll 4
    for (int u = 0; u < NU; u++)
        acc = fmaf(g_z[u * BATCH + tid], wfs[u], acc);

    out[tid * NCLS + c] = acc;
}

// ---------------------------------------------------------------------------
extern "C" void kernel_launch(void* const* d_in, const int* in_sizes, int n_in,
                              void* d_out, int out_size)
{
    const float* x   = (const float*)d_in[0];
    const float* w1  = (const float*)d_in[1];
    const float* b1  = (const float*)d_in[2];
    const float* g1  = (const float*)d_in[3];
    const float* be1 = (const float*)d_in[4];
    const float* m1  = (const float*)d_in[5];
    const float* v1  = (const float*)d_in[6];
    const float* w2  = (const float*)d_in[7];
    const float* b2  = (const float*)d_in[8];
    const float* g2  = (const float*)d_in[9];
    const float* be2 = (const float*)d_in[10];
    const float* m2  = (const float*)d_in[11];
    const float* v2  = (const float*)d_in[12];
    const float* w3  = (const float*)d_in[13];
    const float* b3  = (const float*)d_in[14];
    const float* g3  = (const float*)d_in[15];
    const float* be3 = (const float*)d_in[16];
    const float* m3  = (const float*)d_in[17];
    const float* v3  = (const float*)d_in[18];
    const float* wf  = (const float*)d_in[19];
    const float* bf  = (const float*)d_in[20];
    float* out = (float*)d_out;

    conv_pool_kernel<<<dim3(NU / UPB, BATCH), TA>>>(x, w1, b1, g1, be1, m1, v1);
    unit_mlp_kernel<<<NU, BATCH>>>(w2, b2, g2, be2, m2, v2,
                                   w3, b3, g3, be3, m3, v3);
    final_linear_kernel<<<NCLS, BATCH>>>(wf, bf, out);
}